// round 13
// baseline (speedup 1.0000x reference)
#include <cuda_runtime.h>
#include <cuda_bf16.h>
#include <cstdint>

#define BATCH 4
#define SEQ   4096
#define CDIM  256
#define HEADS 4
#define HDIM  64
#define SCALE 0.125f
#define LOG2E 1.44269504f
#define BH    (BATCH*HEADS)

// attention tiling
#define TK    64
#define KSTR  72                  // floats; conflict-free LDS.64
#define VSTR2 68                  // float2; conflict-free LDS.64
#define KBYTES (TK*KSTR*4)
#define VBYTES ((TK/2)*VSTR2*8)
#define BUFBYTES (KBYTES + VBYTES)   // 35840
#define NBUF 3
#define SMEM_ATTN (NBUF*BUFBYTES)    // 107520 B -> 2 CTAs/SM (215KB)
#define NT (SEQ/TK)

// projection GEMM tiling
#define PSTR2 20
#define PBUF (2*128*PSTR2*2)
#define SMEM_PROJ (2*PBUF*4)

#define XGROUPS (BATCH*SEQ*CDIM/8)
#define WGROUPS (CDIM*CDIM/8)
#define PACKTOT (XGROUPS + 4*WGROUPS)

// ---------------------------------------------------------------------------
__device__ float g_q[BH * SEQ * HDIM];
__device__ float g_k[BH * SEQ * HDIM];
__device__ float g_v[BH * SEQ * HDIM];
__device__ float g_ao[BATCH * SEQ * CDIM];     // pair-packed along CDIM
__device__ float g_xp[BATCH * SEQ * CDIM];
__device__ float g_wp[4 * CDIM * CDIM];

// ---------------------------------------------------------------------------
__device__ __forceinline__ float tf32r(float x) {
    uint32_t u; asm("cvt.rna.tf32.f32 %0, %1;" : "=r"(u) : "f"(x));
    return __uint_as_float(u);
}
__device__ __forceinline__ float ex2f(float x) {
    float r; asm("ex2.approx.ftz.f32 %0, %1;" : "=f"(r) : "f"(x));
    return r;
}
__device__ __forceinline__ uint32_t smem_u32(const void* p) {
    uint32_t a;
    asm("{ .reg .u64 t; cvta.to.shared.u64 t, %1; cvt.u32.u64 %0, t; }" : "=r"(a) : "l"(p));
    return a;
}
__device__ __forceinline__ void cpa16(uint32_t dst, const float* src) {
    asm volatile("cp.async.cg.shared.global [%0], [%1], 16;" :: "r"(dst), "l"(src) : "memory");
}
__device__ __forceinline__ void mma_tf32(float (&c)[4], const uint32_t (&a)[4],
                                         uint32_t b0, uint32_t b1) {
    asm("mma.sync.aligned.m16n8k8.row.col.f32.tf32.tf32.f32 "
        "{%0,%1,%2,%3}, {%4,%5,%6,%7}, {%8,%9}, {%0,%1,%2,%3};"
        : "+f"(c[0]), "+f"(c[1]), "+f"(c[2]), "+f"(c[3])
        : "r"(a[0]), "r"(a[1]), "r"(a[2]), "r"(a[3]), "r"(b0), "r"(b1));
}
__device__ __forceinline__ int dpack(int d) {
    return (d & ~7) | ((d & 3) << 1) | ((d >> 2) & 1);
}

// ---------------------------------------------------------------------------
// Prepass: tf32-round + pair-pack x and the four weight matrices.
// ---------------------------------------------------------------------------
__global__ void pack_tf32(const float* __restrict__ x,
                          const float* __restrict__ Wq,
                          const float* __restrict__ Wk,
                          const float* __restrict__ Wv,
                          const float* __restrict__ Wp)
{
    int i = blockIdx.x * 256 + threadIdx.x;
    if (i >= PACKTOT) return;
    const float* src;
    float* dst;
    if (i < XGROUPS) {
        src = x; dst = g_xp;
    } else {
        int j = i - XGROUPS;
        int w = j >> 13;
        i = j & (WGROUPS - 1);
        src = (w == 0) ? Wq : (w == 1) ? Wk : (w == 2) ? Wv : Wp;
        dst = g_wp + w * (CDIM * CDIM);
    }
    float4 a = ((const float4*)src)[i * 2];
    float4 b = ((const float4*)src)[i * 2 + 1];
    float4 o0 = make_float4(tf32r(a.x), tf32r(b.x), tf32r(a.y), tf32r(b.y));
    float4 o1 = make_float4(tf32r(a.z), tf32r(b.z), tf32r(a.w), tf32r(b.w));
    ((float4*)dst)[i * 2]     = o0;
    ((float4*)dst)[i * 2 + 1] = o1;
}

// ---------------------------------------------------------------------------
// tf32 mma projection core on PACKED operands
// ---------------------------------------------------------------------------
struct ProjAcc { float c[2][8][4]; };

__device__ __forceinline__ void proj_core(const float* __restrict__ A,
                                          const float* __restrict__ Bm,
                                          int m0, int n0, float* smp, ProjAcc& P)
{
    const int tid = threadIdx.x, lane = tid & 31, warp = tid >> 5;
    const int g = lane >> 2, qd = lane & 3;
    const int wm = warp >> 1, wn = warp & 1;
    const uint32_t smb = smem_u32(smp);

    #pragma unroll
    for (int m = 0; m < 2; m++)
        #pragma unroll
        for (int nn = 0; nn < 8; nn++)
            #pragma unroll
            for (int i = 0; i < 4; i++) P.c[m][nn][i] = 0.f;

    auto stage = [&](int kc, int b) {
        uint32_t xb = smb + (uint32_t)(b * PBUF) * 4;
        uint32_t wb = xb + (uint32_t)(128 * PSTR2 * 2) * 4;
        int k0 = kc * 32;
        #pragma unroll
        for (int p = 0; p < 4; p++) {
            int idx = p * 256 + tid;
            int r = idx >> 3, cc = idx & 7;
            cpa16(xb + (uint32_t)(r * (PSTR2 * 2) + cc * 4) * 4,
                  A  + (size_t)(m0 + r) * CDIM + k0 + cc * 4);
            cpa16(wb + (uint32_t)(r * (PSTR2 * 2) + cc * 4) * 4,
                  Bm + (size_t)(n0 + r) * CDIM + k0 + cc * 4);
        }
    };

    stage(0, 0);
    asm volatile("cp.async.commit_group;" ::: "memory");

    for (int kc = 0; kc < CDIM / 32; kc++) {
        int b = kc & 1;
        if (kc + 1 < CDIM / 32) {
            stage(kc + 1, b ^ 1);
            asm volatile("cp.async.commit_group;" ::: "memory");
            asm volatile("cp.async.wait_group 1;" ::: "memory");
        } else {
            asm volatile("cp.async.wait_group 0;" ::: "memory");
        }
        __syncthreads();

        const float2* Xs2 = (const float2*)(smp + b * PBUF);
        const float2* Ws2 = Xs2 + 128 * PSTR2;

        #pragma unroll
        for (int kk = 0; kk < 4; kk++) {
            uint32_t am[2][4];
            #pragma unroll
            for (int m = 0; m < 2; m++) {
                int r0 = wm * 32 + m * 16;
                float2 qa = Xs2[(r0 + g    ) * PSTR2 + kk * 4 + qd];
                float2 qb = Xs2[(r0 + g + 8) * PSTR2 + kk * 4 + qd];
                am[m][0] = __float_as_uint(qa.x);
                am[m][1] = __float_as_uint(qb.x);
                am[m][2] = __float_as_uint(qa.y);
                am[m][3] = __float_as_uint(qb.y);
            }
            #pragma unroll
            for (int nn = 0; nn < 8; nn++) {
                float2 bb = Ws2[(wn * 64 + nn * 8 + g) * PSTR2 + kk * 4 + qd];
                uint32_t b0 = __float_as_uint(bb.x);
                uint32_t b1 = __float_as_uint(bb.y);
                mma_tf32(P.c[0][nn], am[0], b0, b1);
                mma_tf32(P.c[1][nn], am[1], b0, b1);
            }
        }
        __syncthreads();
    }
}

// grid (2, 128, 3)
__global__ void __launch_bounds__(256) proj_qkv()
{
    extern __shared__ float smp[];
    const int z = blockIdx.z;
    const float* W = g_wp + z * (CDIM * CDIM);
    float* dst     = (z == 0) ? g_q : (z == 1) ? g_k : g_v;
    const float sc = (z == 0) ? (SCALE * LOG2E) : 1.0f;
    const int m0 = blockIdx.y * 128, n0 = blockIdx.x * 128;

    ProjAcc P;
    proj_core(g_xp, W, m0, n0, smp, P);

    const int lane = threadIdx.x & 31, warp = threadIdx.x >> 5;
    const int g = lane >> 2, qd = lane & 3;
    const int wm = warp >> 1, wn = warp & 1;

    #pragma unroll
    for (int m = 0; m < 2; m++)
        #pragma unroll
        for (int rr = 0; rr < 2; rr++) {
            int mg = m0 + wm * 32 + m * 16 + g + rr * 8;
            int b = mg >> 12, n = mg & (SEQ - 1);
            #pragma unroll
            for (int nn = 0; nn < 8; nn++) {
                int col = n0 + wn * 64 + nn * 8 + qd * 2;
                int h = col >> 6, d = col & 63;
                float v0 = tf32r(P.c[m][nn][rr * 2 + 0] * sc);
                float v1 = tf32r(P.c[m][nn][rr * 2 + 1] * sc);
                size_t bh = (size_t)(b * HEADS + h);
                if (z < 2) {
                    float* rowp = dst + (bh * SEQ + n) * HDIM;
                    rowp[dpack(d)]     = v0;
                    rowp[dpack(d + 1)] = v1;
                } else {
                    float* vp = dst + (bh * (SEQ / 2) + (n >> 1)) * (HDIM * 2) + (n & 1);
                    vp[d * 2]       = v0;
                    vp[(d + 1) * 2] = v1;
                }
            }
        }
}

// grid (2, 128)
__global__ void __launch_bounds__(256) proj_out(const float* __restrict__ bp,
                                                float* __restrict__ out)
{
    extern __shared__ float smp[];
    const int m0 = blockIdx.y * 128, n0 = blockIdx.x * 128;

    ProjAcc P;
    proj_core(g_ao, g_wp + 3 * (CDIM * CDIM), m0, n0, smp, P);

    const int lane = threadIdx.x & 31, warp = threadIdx.x >> 5;
    const int g = lane >> 2, qd = lane & 3;
    const int wm = warp >> 1, wn = warp & 1;

    #pragma unroll
    for (int m = 0; m < 2; m++)
        #pragma unroll
        for (int rr = 0; rr < 2; rr++) {
            int mg = m0 + wm * 32 + m * 16 + g + rr * 8;
            #pragma unroll
            for (int nn = 0; nn < 8; nn++) {
                int col = n0 + wn * 64 + nn * 8 + qd * 2;
                float2 bb = *(const float2*)(bp + col);
                float2 v = make_float2(P.c[m][nn][rr * 2 + 0] + bb.x,
                                       P.c[m][nn][rr * 2 + 1] + bb.y);
                *(float2*)&out[(size_t)mg * CDIM + col] = v;
            }
        }
}

// ---------------------------------------------------------------------------
// tf32 mma.sync flash attention: 8 warps x M=16 rows (halved warp tile ->
// ~110 live regs -> 4 warps/SMSP at 2 CTAs/SM), 3-stage cp.async pipeline,
// one barrier per tile, shuffle-free P feed, ex2 softmax.
// grid = (SEQ/128, BH), block = 256
// ---------------------------------------------------------------------------
__global__ void __launch_bounds__(256, 2) attn_mma()
{
    extern __shared__ float sm[];
    const int tid = threadIdx.x, lane = tid & 31, warp = tid >> 5;
    const int g = lane >> 2, qd = lane & 3;
    const int bh = blockIdx.y, q0 = blockIdx.x * 128;

    const float2* qg2 = (const float2*)(g_q + ((size_t)bh * SEQ + q0 + warp * 16) * HDIM);
    const float*  kg  = g_k + (size_t)bh * SEQ * HDIM;
    const float*  vgp = g_v + (size_t)bh * SEQ * HDIM;

    // persistent Q A-fragments: 16 rows/warp -> qf[kk][4]
    uint32_t qf[8][4];
    #pragma unroll
    for (int kk = 0; kk < 8; kk++) {
        float2 qa = qg2[(g    ) * 32 + kk * 4 + qd];
        float2 qb = qg2[(g + 8) * 32 + kk * 4 + qd];
        qf[kk][0] = __float_as_uint(qa.x);
        qf[kk][1] = __float_as_uint(qb.x);
        qf[kk][2] = __float_as_uint(qa.y);
        qf[kk][3] = __float_as_uint(qb.y);
    }

    float o[8][4] = {};
    float ls[2] = {0.f, 0.f};

    const uint32_t smb = smem_u32(sm);

    auto stage = [&](int t4, int buf) {
        uint32_t kdst = smb + (uint32_t)buf * BUFBYTES;
        uint32_t vdst = kdst + KBYTES;
        int j0 = t4 * TK;
        #pragma unroll
        for (int i = 0; i < 4; i++) {
            int idx = i * 256 + tid;
            int r = idx >> 4, c = idx & 15;
            cpa16(kdst + (uint32_t)(r * KSTR + c * 4) * 4, kg + (size_t)(j0 + r) * 64 + c * 4);
            int r2 = idx >> 5, c2 = idx & 31;
            cpa16(vdst + (uint32_t)(r2 * (VSTR2 * 2) + c2 * 4) * 4,
                  vgp + (size_t)(j0 / 2 + r2) * 128 + c2 * 4);
        }
    };

    stage(0, 0);
    asm volatile("cp.async.commit_group;" ::: "memory");
    stage(1, 1);
    asm volatile("cp.async.commit_group;" ::: "memory");

    int buf = 0, bnext = 2;

    for (int t = 0; t < NT; t++) {
        if (t < NT - 1) {
            asm volatile("cp.async.wait_group 1;" ::: "memory");
        } else {
            asm volatile("cp.async.wait_group 0;" ::: "memory");
        }
        __syncthreads();   // tile t visible; frees buffer bnext

        if (t + 2 < NT) {
            stage(t + 2, bnext);
            asm volatile("cp.async.commit_group;" ::: "memory");
        }

        const float*  Ks  = sm + buf * (BUFBYTES / 4);
        const float2* Vs2 = (const float2*)(Ks + KBYTES / 4);

        #pragma unroll
        for (int nn = 0; nn < 8; nn++) {
            // ---- S = Q K^T (two 4-deep chains) ----
            float ca[4] = {}, cb[4] = {};
            const float2* kb2 = (const float2*)Ks + (nn * 8 + g) * (KSTR / 2) + qd;
            #pragma unroll
            for (int kk = 0; kk < 4; kk++) {
                float2 b01 = kb2[kk * 4];
                mma_tf32(ca, qf[kk], __float_as_uint(b01.x), __float_as_uint(b01.y));
            }
            #pragma unroll
            for (int kk = 4; kk < 8; kk++) {
                float2 b01 = kb2[kk * 4];
                mma_tf32(cb, qf[kk], __float_as_uint(b01.x), __float_as_uint(b01.y));
            }

            // ---- exp (logits pre-scaled by log2e) + row sums ----
            float e[4];
            #pragma unroll
            for (int i = 0; i < 4; i++) e[i] = ex2f(ca[i] + cb[i]);
            ls[0] += e[0] + e[1];
            ls[1] += e[2] + e[3];

            // ---- PV A-fragment = register rename of exp'ed C-fragment ----
            uint32_t pa[4];
            pa[0] = __float_as_uint(e[0]); pa[1] = __float_as_uint(e[2]);
            pa[2] = __float_as_uint(e[1]); pa[3] = __float_as_uint(e[3]);

            // ---- O += P V ----
            const float2* vb2 = Vs2 + (nn * 4 + qd) * VSTR2 + g;
            #pragma unroll
            for (int dn = 0; dn < 8; dn++) {
                float2 v01 = vb2[dn * 8];
                mma_tf32(o[dn], pa, __float_as_uint(v01.x), __float_as_uint(v01.y));
            }
        }

        buf = (buf == 2) ? 0 : buf + 1;
        bnext = (bnext == 2) ? 0 : bnext + 1;
    }

    // reduce row sums across the 4 quad lanes (disjoint cols)
    #pragma unroll
    for (int i = 0; i < 2; i++) {
        ls[i] += __shfl_xor_sync(0xffffffffu, ls[i], 1);
        ls[i] += __shfl_xor_sync(0xffffffffu, ls[i], 2);
    }

    const int b = bh >> 2, h = bh & 3;
    #pragma unroll
    for (int rr = 0; rr < 2; rr++) {
        int row = q0 + warp * 16 + g + rr * 8;
        float iv = 1.f / ls[rr];
        float* aop = g_ao + ((size_t)(b * SEQ) + row) * CDIM + h * 64;
        #pragma unroll
        for (int dn = 0; dn < 8; dn++) {
            int d = dn * 8 + qd * 2;
            aop[(dn * 8) + dpack(d & 7)]       = tf32r(o[dn][rr * 2 + 0] * iv);
            aop[(dn * 8) + dpack((d + 1) & 7)] = tf32r(o[dn][rr * 2 + 1] * iv);
        }
    }
}

// ---------------------------------------------------------------------------
extern "C" void kernel_launch(void* const* d_in, const int* in_sizes, int n_in,
                              void* d_out, int out_size)
{
    (void)in_sizes; (void)n_in; (void)out_size;
    const float* x  = (const float*)d_in[0];
    const float* Wq = (const float*)d_in[1];
    const float* Wk = (const float*)d_in[2];
    const float* Wv = (const float*)d_in[3];
    const float* Wp = (const float*)d_in[4];
    const float* bp = (const float*)d_in[5];
    float* out = (float*)d_out;

    cudaFuncSetAttribute(proj_qkv, cudaFuncAttributeMaxDynamicSharedMemorySize, SMEM_PROJ);
    cudaFuncSetAttribute(proj_out, cudaFuncAttributeMaxDynamicSharedMemorySize, SMEM_PROJ);
    cudaFuncSetAttribute(attn_mma, cudaFuncAttributeMaxDynamicSharedMemorySize, SMEM_ATTN);

    pack_tf32<<<(PACKTOT + 255) / 256, 256>>>(x, Wq, Wk, Wv, Wp);

    dim3 gq(CDIM / 128, (BATCH * SEQ) / 128, 3);
    proj_qkv<<<gq, 256, SMEM_PROJ>>>();

    dim3 ga(SEQ / 128, BH);
    attn_mma<<<ga, 256, SMEM_ATTN>>>();

    dim3 go(CDIM / 128, (BATCH * SEQ) / 128);
    proj_out<<<go, 256, SMEM_PROJ>>>(bp, out);
}

// round 14
// speedup vs baseline: 1.0601x; 1.0601x over previous
#include <cuda_runtime.h>
#include <cuda_bf16.h>
#include <cstdint>

#define BATCH 4
#define SEQ   4096
#define CDIM  256
#define HEADS 4
#define HDIM  64
#define SCALE 0.125f
#define LOG2E 1.44269504f
#define BH    (BATCH*HEADS)

// attention tiling (R10 champion config)
#define TK    64
#define KSTR  72                  // floats; conflict-free LDS.64
#define VSTR2 68                  // float2; conflict-free LDS.64
#define KBYTES (TK*KSTR*4)
#define VBYTES ((TK/2)*VSTR2*8)
#define BUFBYTES (KBYTES + VBYTES)   // 35840
#define NBUF 3
#define SMEM_ATTN (NBUF*BUFBYTES)    // 107520 B -> 2 CTAs/SM
#define NT (SEQ/TK)

// projection GEMM tiling: 128x128 tile, k-chunk 32, packed tf32 operands,
// 512 threads (16 warps, 4x4 warp grid, 32x32 warp tile)
#define PSTR2 20
#define PBUF (2*128*PSTR2*2)
#define SMEM_PROJ (2*PBUF*4)      // 81920 B

#define XGROUPS (BATCH*SEQ*CDIM/8)
#define WGROUPS (CDIM*CDIM/8)
#define PACKTOT (XGROUPS + 4*WGROUPS)

// ---------------------------------------------------------------------------
__device__ float g_q[BH * SEQ * HDIM];
__device__ float g_k[BH * SEQ * HDIM];
__device__ float g_v[BH * SEQ * HDIM];
__device__ float g_ao[BATCH * SEQ * CDIM];     // pair-packed along CDIM
__device__ float g_xp[BATCH * SEQ * CDIM];
__device__ float g_wp[4 * CDIM * CDIM];

// ---------------------------------------------------------------------------
__device__ __forceinline__ float tf32r(float x) {
    uint32_t u; asm("cvt.rna.tf32.f32 %0, %1;" : "=r"(u) : "f"(x));
    return __uint_as_float(u);
}
__device__ __forceinline__ float ex2f(float x) {
    float r; asm("ex2.approx.ftz.f32 %0, %1;" : "=f"(r) : "f"(x));
    return r;
}
__device__ __forceinline__ uint32_t smem_u32(const void* p) {
    uint32_t a;
    asm("{ .reg .u64 t; cvta.to.shared.u64 t, %1; cvt.u32.u64 %0, t; }" : "=r"(a) : "l"(p));
    return a;
}
__device__ __forceinline__ void cpa16(uint32_t dst, const float* src) {
    asm volatile("cp.async.cg.shared.global [%0], [%1], 16;" :: "r"(dst), "l"(src) : "memory");
}
__device__ __forceinline__ void mma_tf32(float (&c)[4], const uint32_t (&a)[4],
                                         uint32_t b0, uint32_t b1) {
    asm("mma.sync.aligned.m16n8k8.row.col.f32.tf32.tf32.f32 "
        "{%0,%1,%2,%3}, {%4,%5,%6,%7}, {%8,%9}, {%0,%1,%2,%3};"
        : "+f"(c[0]), "+f"(c[1]), "+f"(c[2]), "+f"(c[3])
        : "r"(a[0]), "r"(a[1]), "r"(a[2]), "r"(a[3]), "r"(b0), "r"(b1));
}
__device__ __forceinline__ int dpack(int d) {
    return (d & ~7) | ((d & 3) << 1) | ((d >> 2) & 1);
}

// ---------------------------------------------------------------------------
// Prepass: tf32-round + pair-pack x and the four weight matrices.
// ---------------------------------------------------------------------------
__global__ void pack_tf32(const float* __restrict__ x,
                          const float* __restrict__ Wq,
                          const float* __restrict__ Wk,
                          const float* __restrict__ Wv,
                          const float* __restrict__ Wp)
{
    int i = blockIdx.x * 256 + threadIdx.x;
    if (i >= PACKTOT) return;
    const float* src;
    float* dst;
    if (i < XGROUPS) {
        src = x; dst = g_xp;
    } else {
        int j = i - XGROUPS;
        int w = j >> 13;
        i = j & (WGROUPS - 1);
        src = (w == 0) ? Wq : (w == 1) ? Wk : (w == 2) ? Wv : Wp;
        dst = g_wp + w * (CDIM * CDIM);
    }
    float4 a = ((const float4*)src)[i * 2];
    float4 b = ((const float4*)src)[i * 2 + 1];
    float4 o0 = make_float4(tf32r(a.x), tf32r(b.x), tf32r(a.y), tf32r(b.y));
    float4 o1 = make_float4(tf32r(a.z), tf32r(b.z), tf32r(a.w), tf32r(b.w));
    ((float4*)dst)[i * 2]     = o0;
    ((float4*)dst)[i * 2 + 1] = o1;
}

// ---------------------------------------------------------------------------
// tf32 mma projection core: 512 threads, 4x4 warp grid, 32x32 warp tile.
// Packed operands -> zero cvt, all-LDS.64 fragments.
// ---------------------------------------------------------------------------
struct ProjAcc { float c[2][4][4]; };   // [m-block][n-block][frag]

__device__ __forceinline__ void proj_core(const float* __restrict__ A,
                                          const float* __restrict__ Bm,
                                          int m0, int n0, float* smp, ProjAcc& P)
{
    const int tid = threadIdx.x, lane = tid & 31, warp = tid >> 5;
    const int g = lane >> 2, qd = lane & 3;
    const int wm = warp >> 2, wn = warp & 3;
    const uint32_t smb = smem_u32(smp);

    #pragma unroll
    for (int m = 0; m < 2; m++)
        #pragma unroll
        for (int nn = 0; nn < 4; nn++)
            #pragma unroll
            for (int i = 0; i < 4; i++) P.c[m][nn][i] = 0.f;

    auto stage = [&](int kc, int b) {
        uint32_t xb = smb + (uint32_t)(b * PBUF) * 4;
        uint32_t wb = xb + (uint32_t)(128 * PSTR2 * 2) * 4;
        int k0 = kc * 32;
        #pragma unroll
        for (int p = 0; p < 2; p++) {
            int idx = p * 512 + tid;
            int r = idx >> 3, cc = idx & 7;
            cpa16(xb + (uint32_t)(r * (PSTR2 * 2) + cc * 4) * 4,
                  A  + (size_t)(m0 + r) * CDIM + k0 + cc * 4);
            cpa16(wb + (uint32_t)(r * (PSTR2 * 2) + cc * 4) * 4,
                  Bm + (size_t)(n0 + r) * CDIM + k0 + cc * 4);
        }
    };

    stage(0, 0);
    asm volatile("cp.async.commit_group;" ::: "memory");

    for (int kc = 0; kc < CDIM / 32; kc++) {
        int b = kc & 1;
        if (kc + 1 < CDIM / 32) {
            stage(kc + 1, b ^ 1);
            asm volatile("cp.async.commit_group;" ::: "memory");
            asm volatile("cp.async.wait_group 1;" ::: "memory");
        } else {
            asm volatile("cp.async.wait_group 0;" ::: "memory");
        }
        __syncthreads();

        const float2* Xs2 = (const float2*)(smp + b * PBUF);
        const float2* Ws2 = Xs2 + 128 * PSTR2;

        #pragma unroll
        for (int kk = 0; kk < 4; kk++) {
            uint32_t am[2][4];
            #pragma unroll
            for (int m = 0; m < 2; m++) {
                int r0 = wm * 32 + m * 16;
                float2 qa = Xs2[(r0 + g    ) * PSTR2 + kk * 4 + qd];
                float2 qb = Xs2[(r0 + g + 8) * PSTR2 + kk * 4 + qd];
                am[m][0] = __float_as_uint(qa.x);
                am[m][1] = __float_as_uint(qb.x);
                am[m][2] = __float_as_uint(qa.y);
                am[m][3] = __float_as_uint(qb.y);
            }
            #pragma unroll
            for (int nn = 0; nn < 4; nn++) {
                float2 bb = Ws2[(wn * 32 + nn * 8 + g) * PSTR2 + kk * 4 + qd];
                uint32_t b0 = __float_as_uint(bb.x);
                uint32_t b1 = __float_as_uint(bb.y);
                mma_tf32(P.c[0][nn], am[0], b0, b1);
                mma_tf32(P.c[1][nn], am[1], b0, b1);
            }
        }
        __syncthreads();
    }
}

// grid (2, 128, 3), block 512
__global__ void __launch_bounds__(512) proj_qkv()
{
    extern __shared__ float smp[];
    const int z = blockIdx.z;
    const float* W = g_wp + z * (CDIM * CDIM);
    float* dst     = (z == 0) ? g_q : (z == 1) ? g_k : g_v;
    const float sc = (z == 0) ? (SCALE * LOG2E) : 1.0f;
    const int m0 = blockIdx.y * 128, n0 = blockIdx.x * 128;

    ProjAcc P;
    proj_core(g_xp, W, m0, n0, smp, P);

    const int lane = threadIdx.x & 31, warp = threadIdx.x >> 5;
    const int g = lane >> 2, qd = lane & 3;
    const int wm = warp >> 2, wn = warp & 3;

    #pragma unroll
    for (int m = 0; m < 2; m++)
        #pragma unroll
        for (int rr = 0; rr < 2; rr++) {
            int mg = m0 + wm * 32 + m * 16 + g + rr * 8;
            int b = mg >> 12, n = mg & (SEQ - 1);
            #pragma unroll
            for (int nn = 0; nn < 4; nn++) {
                int col = n0 + wn * 32 + nn * 8 + qd * 2;
                int h = col >> 6, d = col & 63;
                float v0 = tf32r(P.c[m][nn][rr * 2 + 0] * sc);
                float v1 = tf32r(P.c[m][nn][rr * 2 + 1] * sc);
                size_t bh = (size_t)(b * HEADS + h);
                if (z < 2) {
                    float* rowp = dst + (bh * SEQ + n) * HDIM;
                    rowp[dpack(d)]     = v0;
                    rowp[dpack(d + 1)] = v1;
                } else {
                    float* vp = dst + (bh * (SEQ / 2) + (n >> 1)) * (HDIM * 2) + (n & 1);
                    vp[d * 2]       = v0;
                    vp[(d + 1) * 2] = v1;
                }
            }
        }
}

// grid (2, 128), block 512
__global__ void __launch_bounds__(512) proj_out(const float* __restrict__ bp,
                                                float* __restrict__ out)
{
    extern __shared__ float smp[];
    const int m0 = blockIdx.y * 128, n0 = blockIdx.x * 128;

    ProjAcc P;
    proj_core(g_ao, g_wp + 3 * (CDIM * CDIM), m0, n0, smp, P);

    const int lane = threadIdx.x & 31, warp = threadIdx.x >> 5;
    const int g = lane >> 2, qd = lane & 3;
    const int wm = warp >> 2, wn = warp & 3;

    #pragma unroll
    for (int m = 0; m < 2; m++)
        #pragma unroll
        for (int rr = 0; rr < 2; rr++) {
            int mg = m0 + wm * 32 + m * 16 + g + rr * 8;
            #pragma unroll
            for (int nn = 0; nn < 4; nn++) {
                int col = n0 + wn * 32 + nn * 8 + qd * 2;
                float2 bb = *(const float2*)(bp + col);
                float2 v = make_float2(P.c[m][nn][rr * 2 + 0] + bb.x,
                                       P.c[m][nn][rr * 2 + 1] + bb.y);
                *(float2*)&out[(size_t)mg * CDIM + col] = v;
            }
        }
}

// ---------------------------------------------------------------------------
// tf32 mma.sync flash attention — R10 champion config, verbatim.
// grid = (SEQ/128, BH), block = 128, 2 CTAs/SM, 3-stage pipeline.
// ---------------------------------------------------------------------------
__global__ void __launch_bounds__(128, 2) attn_mma()
{
    extern __shared__ float sm[];
    const int tid = threadIdx.x, lane = tid & 31, warp = tid >> 5;
    const int g = lane >> 2, qd = lane & 3;
    const int bh = blockIdx.y, q0 = blockIdx.x * 128;

    const float2* qg2 = (const float2*)(g_q + ((size_t)bh * SEQ + q0 + warp * 32) * HDIM);
    const float*  kg  = g_k + (size_t)bh * SEQ * HDIM;
    const float*  vgp = g_v + (size_t)bh * SEQ * HDIM;

    uint32_t qf[2][8][4];
    #pragma unroll
    for (int m = 0; m < 2; m++)
        #pragma unroll
        for (int kk = 0; kk < 8; kk++) {
            float2 qa = qg2[(m * 16 + g    ) * 32 + kk * 4 + qd];
            float2 qb = qg2[(m * 16 + g + 8) * 32 + kk * 4 + qd];
            qf[m][kk][0] = __float_as_uint(qa.x);
            qf[m][kk][1] = __float_as_uint(qb.x);
            qf[m][kk][2] = __float_as_uint(qa.y);
            qf[m][kk][3] = __float_as_uint(qb.y);
        }

    float o[2][8][4] = {};
    float ls[4] = {0.f, 0.f, 0.f, 0.f};

    const uint32_t smb = smem_u32(sm);

    auto stage = [&](int t4, int buf) {
        uint32_t kdst = smb + (uint32_t)buf * BUFBYTES;
        uint32_t vdst = kdst + KBYTES;
        int j0 = t4 * TK;
        #pragma unroll
        for (int i = 0; i < 8; i++) {
            int idx = i * 128 + tid;
            int r = idx >> 4, c = idx & 15;
            cpa16(kdst + (uint32_t)(r * KSTR + c * 4) * 4, kg + (size_t)(j0 + r) * 64 + c * 4);
            int r2 = idx >> 5, c2 = idx & 31;
            cpa16(vdst + (uint32_t)(r2 * (VSTR2 * 2) + c2 * 4) * 4,
                  vgp + (size_t)(j0 / 2 + r2) * 128 + c2 * 4);
        }
    };

    stage(0, 0);
    asm volatile("cp.async.commit_group;" ::: "memory");
    stage(1, 1);
    asm volatile("cp.async.commit_group;" ::: "memory");

    int buf = 0, bnext = 2;

    for (int t = 0; t < NT; t++) {
        if (t < NT - 1) {
            asm volatile("cp.async.wait_group 1;" ::: "memory");
        } else {
            asm volatile("cp.async.wait_group 0;" ::: "memory");
        }
        __syncthreads();

        if (t + 2 < NT) {
            stage(t + 2, bnext);
            asm volatile("cp.async.commit_group;" ::: "memory");
        }

        const float*  Ks  = sm + buf * (BUFBYTES / 4);
        const float2* Vs2 = (const float2*)(Ks + KBYTES / 4);

        #pragma unroll
        for (int nn = 0; nn < 8; nn++) {
            float c0a[4] = {}, c0b[4] = {}, c1a[4] = {}, c1b[4] = {};
            const float2* kb2 = (const float2*)Ks + (nn * 8 + g) * (KSTR / 2) + qd;
            #pragma unroll
            for (int kk = 0; kk < 4; kk++) {
                float2 b01 = kb2[kk * 4];
                uint32_t b0 = __float_as_uint(b01.x);
                uint32_t b1 = __float_as_uint(b01.y);
                mma_tf32(c0a, qf[0][kk], b0, b1);
                mma_tf32(c1a, qf[1][kk], b0, b1);
            }
            #pragma unroll
            for (int kk = 4; kk < 8; kk++) {
                float2 b01 = kb2[kk * 4];
                uint32_t b0 = __float_as_uint(b01.x);
                uint32_t b1 = __float_as_uint(b01.y);
                mma_tf32(c0b, qf[0][kk], b0, b1);
                mma_tf32(c1b, qf[1][kk], b0, b1);
            }

            float e0[4], e1[4];
            #pragma unroll
            for (int i = 0; i < 4; i++) {
                e0[i] = ex2f(c0a[i] + c0b[i]);
                e1[i] = ex2f(c1a[i] + c1b[i]);
            }
            ls[0] += e0[0] + e0[1];  ls[1] += e0[2] + e0[3];
            ls[2] += e1[0] + e1[1];  ls[3] += e1[2] + e1[3];

            uint32_t pa0[4], pa1[4];
            pa0[0] = __float_as_uint(e0[0]); pa0[1] = __float_as_uint(e0[2]);
            pa0[2] = __float_as_uint(e0[1]); pa0[3] = __float_as_uint(e0[3]);
            pa1[0] = __float_as_uint(e1[0]); pa1[1] = __float_as_uint(e1[2]);
            pa1[2] = __float_as_uint(e1[1]); pa1[3] = __float_as_uint(e1[3]);

            const float2* vb2 = Vs2 + (nn * 4 + qd) * VSTR2 + g;
            #pragma unroll
            for (int dn = 0; dn < 8; dn++) {
                float2 v01 = vb2[dn * 8];
                uint32_t b0 = __float_as_uint(v01.x);
                uint32_t b1 = __float_as_uint(v01.y);
                mma_tf32(o[0][dn], pa0, b0, b1);
                mma_tf32(o[1][dn], pa1, b0, b1);
            }
        }

        buf = (buf == 2) ? 0 : buf + 1;
        bnext = (bnext == 2) ? 0 : bnext + 1;
    }

    #pragma unroll
    for (int i = 0; i < 4; i++) {
        ls[i] += __shfl_xor_sync(0xffffffffu, ls[i], 1);
        ls[i] += __shfl_xor_sync(0xffffffffu, ls[i], 2);
    }

    const int b = bh >> 2, h = bh & 3;
    #pragma unroll
    for (int m = 0; m < 2; m++)
        #pragma unroll
        for (int rr = 0; rr < 2; rr++) {
            int row = q0 + warp * 32 + m * 16 + g + rr * 8;
            float iv = 1.f / ls[m * 2 + rr];
            float* aop = g_ao + ((size_t)(b * SEQ) + row) * CDIM + h * 64;
            #pragma unroll
            for (int dn = 0; dn < 8; dn++) {
                int d = dn * 8 + qd * 2;
                aop[(dn * 8) + dpack(d & 7)]       = tf32r(o[m][dn][rr * 2 + 0] * iv);
                aop[(dn * 8) + dpack((d + 1) & 7)] = tf32r(o[m][dn][rr * 2 + 1] * iv);
            }
        }
}

// ---------------------------------------------------------------------------
extern "C" void kernel_launch(void* const* d_in, const int* in_sizes, int n_in,
                              void* d_out, int out_size)
{
    (void)in_sizes; (void)n_in; (void)out_size;
    const float* x  = (const float*)d_in[0];
    const float* Wq = (const float*)d_in[1];
    const float* Wk = (const float*)d_in[2];
    const float* Wv = (const float*)d_in[3];
    const float* Wp = (const float*)d_in[4];
    const float* bp = (const float*)d_in[5];
    float* out = (float*)d_out;

    cudaFuncSetAttribute(proj_qkv, cudaFuncAttributeMaxDynamicSharedMemorySize, SMEM_PROJ);
    cudaFuncSetAttribute(proj_out, cudaFuncAttributeMaxDynamicSharedMemorySize, SMEM_PROJ);
    cudaFuncSetAttribute(attn_mma, cudaFuncAttributeMaxDynamicSharedMemorySize, SMEM_ATTN);

    pack_tf32<<<(PACKTOT + 255) / 256, 256>>>(x, Wq, Wk, Wv, Wp);

    dim3 gq(CDIM / 128, (BATCH * SEQ) / 128, 3);
    proj_qkv<<<gq, 512, SMEM_PROJ>>>();

    dim3 ga(SEQ / 128, BH);
    attn_mma<<<ga, 128, SMEM_ATTN>>>();

    dim3 go(CDIM / 128, (BATCH * SEQ) / 128);
    proj_out<<<go, 512, SMEM_PROJ>>>(bp, out);
}

// round 15
// speedup vs baseline: 1.9887x; 1.8760x over previous
#include <cuda_runtime.h>
#include <cuda_fp16.h>
#include <cstdint>

#define BATCH 4
#define SEQ   4096
#define CDIM  256
#define HEADS 4
#define HDIM  64
#define SCALE 0.125f
#define LOG2E 1.44269504f
#define BH    (BATCH*HEADS)

// attention tiling (fp16): K tile 64x64 half, V tile 16 fused-rows x 512B
#define KSTR8 20                    // K smem row stride in 8B units (160B)
#define VSTR8 68                    // V smem row stride in 8B units (544B)
#define KBYTES (64*KSTR8*8)         // 10240
#define VBYTES (16*VSTR8*8)         // 8704
#define BUFBYTES (KBYTES + VBYTES)  // 18944
#define NBUF 3
#define SMEM_ATTN (NBUF*BUFBYTES)   // 56832 B
#define NT (SEQ/64)

// projection tiling (fp16): 128x128 tile, k-chunk 32, row stride 12 (8B units)
#define PSTR8 12
#define PBUFB (2*128*PSTR8*8)       // 24576 B per buffer
#define SMEM_PROJ (2*PBUFB)         // 49152 B

#define XGRP (BATCH*SEQ*CDIM/16)    // 262144 16-element groups
#define WGRP (CDIM*CDIM/16)         // 4096
#define PACKTOT (XGRP + 4*WGRP)

// ---------------------------------------------------------------------------
// Scratch (half). Packing conventions:
//  * "k-pack" along a 256/64-wide dim: for index c, j=c>>1, halves stored at
//    c8=((j>>3)<<2)|(j&3), slot=(j>>2)&1, within-16-group order
//    [c0,c1,c8,c9, c2,c3,c10,c11, c4,c5,c12,c13, c6,c7,c14,c15]
//    -> one 8B elem = f16 A/B fragment pair (b0,b1)/(a0,a2).
//  * V: half2 pairs adjacent kv (r=n>>1), rows (q,q+4) interleaved per
//    8-group: s=(r>>3)*4+(r&3), slot=(r>>2)&1.
// ---------------------------------------------------------------------------
__device__ __half g_qh[BH * SEQ * HDIM];
__device__ __half g_kh[BH * SEQ * HDIM];
__device__ __half g_vh[BH * SEQ * HDIM];
__device__ __half g_aoh[BATCH * SEQ * CDIM];
__device__ __half g_xh[BATCH * SEQ * CDIM];
__device__ __half g_wh[4 * CDIM * CDIM];

// ---------------------------------------------------------------------------
__device__ __forceinline__ float ex2f(float x) {
    float r; asm("ex2.approx.ftz.f32 %0, %1;" : "=f"(r) : "f"(x));
    return r;
}
__device__ __forceinline__ uint32_t smem_u32(const void* p) {
    uint32_t a;
    asm("{ .reg .u64 t; cvta.to.shared.u64 t, %1; cvt.u32.u64 %0, t; }" : "=r"(a) : "l"(p));
    return a;
}
__device__ __forceinline__ void cpa16(uint32_t dst, const void* src) {
    asm volatile("cp.async.cg.shared.global [%0], [%1], 16;" :: "r"(dst), "l"(src) : "memory");
}
__device__ __forceinline__ void mma_f16(float (&c)[4], const uint32_t (&a)[4],
                                        uint32_t b0, uint32_t b1) {
    asm("mma.sync.aligned.m16n8k16.row.col.f32.f16.f16.f32 "
        "{%0,%1,%2,%3}, {%4,%5,%6,%7}, {%8,%9}, {%0,%1,%2,%3};"
        : "+f"(c[0]), "+f"(c[1]), "+f"(c[2]), "+f"(c[3])
        : "r"(a[0]), "r"(a[1]), "r"(a[2]), "r"(a[3]), "r"(b0), "r"(b1));
}
__device__ __forceinline__ uint32_t h2u(__half2 h) {
    return *reinterpret_cast<uint32_t*>(&h);
}

// ---------------------------------------------------------------------------
// Prepass: f16-convert + k-pack x and the four weight matrices.
// Each thread: one 16-float group -> 16 packed halves.
// ---------------------------------------------------------------------------
__global__ void pack_f16(const float* __restrict__ x,
                         const float* __restrict__ Wq,
                         const float* __restrict__ Wk,
                         const float* __restrict__ Wv,
                         const float* __restrict__ Wp)
{
    int i = blockIdx.x * 256 + threadIdx.x;
    if (i >= PACKTOT) return;
    const float* src;
    __half* dst;
    if (i < XGRP) {
        src = x; dst = g_xh;
    } else {
        int j = i - XGRP;
        int w = j >> 12;
        i = j & (WGRP - 1);
        src = (w == 0) ? Wq : (w == 1) ? Wk : (w == 2) ? Wv : Wp;
        dst = g_wh + w * (CDIM * CDIM);
    }
    const float4* s4 = (const float4*)src + (size_t)i * 4;
    float4 A = s4[0], B = s4[1], C = s4[2], D = s4[3];
    __half2 h[8];
    h[0] = __floats2half2_rn(A.x, A.y);  h[1] = __floats2half2_rn(C.x, C.y);
    h[2] = __floats2half2_rn(A.z, A.w);  h[3] = __floats2half2_rn(C.z, C.w);
    h[4] = __floats2half2_rn(B.x, B.y);  h[5] = __floats2half2_rn(D.x, D.y);
    h[6] = __floats2half2_rn(B.z, B.w);  h[7] = __floats2half2_rn(D.z, D.w);
    uint4* d4 = (uint4*)(dst + (size_t)i * 16);
    d4[0] = make_uint4(h2u(h[0]), h2u(h[1]), h2u(h[2]), h2u(h[3]));
    d4[1] = make_uint4(h2u(h[4]), h2u(h[5]), h2u(h[6]), h2u(h[7]));
}

// ---------------------------------------------------------------------------
// fp16 mma projection core: 256 threads (4x2 warps, 32x64 warp tile),
// k-chunk 32 (2 sub-chunks of 16), packed operands, double buffered.
// ---------------------------------------------------------------------------
struct ProjAcc { float c[2][8][4]; };

__device__ __forceinline__ void proj_core(const __half* __restrict__ A,
                                          const __half* __restrict__ Bm,
                                          int m0, int n0, char* smp, ProjAcc& P)
{
    const int tid = threadIdx.x, lane = tid & 31, warp = tid >> 5;
    const int g = lane >> 2, qd = lane & 3;
    const int wm = warp >> 1, wn = warp & 1;
    const uint32_t smb = smem_u32(smp);

    #pragma unroll
    for (int m = 0; m < 2; m++)
        #pragma unroll
        for (int nn = 0; nn < 8; nn++)
            #pragma unroll
            for (int i = 0; i < 4; i++) P.c[m][nn][i] = 0.f;

    auto stage = [&](int kc, int b) {
        uint32_t xb = smb + (uint32_t)(b * PBUFB);
        uint32_t wb = xb + 128 * PSTR8 * 8;
        #pragma unroll
        for (int p = 0; p < 2; p++) {
            int idx = p * 256 + tid;
            int r = idx >> 2, c = idx & 3;
            cpa16(xb + (uint32_t)(r * (PSTR8 * 8) + c * 16),
                  A  + (size_t)(m0 + r) * CDIM + kc * 32 + c * 8);
            cpa16(wb + (uint32_t)(r * (PSTR8 * 8) + c * 16),
                  Bm + (size_t)(n0 + r) * CDIM + kc * 32 + c * 8);
        }
    };

    stage(0, 0);
    asm volatile("cp.async.commit_group;" ::: "memory");

    for (int kc = 0; kc < CDIM / 32; kc++) {
        int b = kc & 1;
        if (kc + 1 < CDIM / 32) {
            stage(kc + 1, b ^ 1);
            asm volatile("cp.async.commit_group;" ::: "memory");
            asm volatile("cp.async.wait_group 1;" ::: "memory");
        } else {
            asm volatile("cp.async.wait_group 0;" ::: "memory");
        }
        __syncthreads();

        const uint2* Xs8 = (const uint2*)(smp + b * PBUFB);
        const uint2* Ws8 = Xs8 + 128 * PSTR8;

        #pragma unroll
        for (int t = 0; t < 2; t++) {
            uint32_t am[2][4];
            #pragma unroll
            for (int m = 0; m < 2; m++) {
                int r0 = wm * 32 + m * 16;
                uint2 ua = Xs8[(r0 + g    ) * PSTR8 + t * 4 + qd];
                uint2 ub = Xs8[(r0 + g + 8) * PSTR8 + t * 4 + qd];
                am[m][0] = ua.x; am[m][1] = ub.x; am[m][2] = ua.y; am[m][3] = ub.y;
            }
            #pragma unroll
            for (int nn = 0; nn < 8; nn++) {
                uint2 wv = Ws8[(wn * 64 + nn * 8 + g) * PSTR8 + t * 4 + qd];
                mma_f16(P.c[0][nn], am[0], wv.x, wv.y);
                mma_f16(P.c[1][nn], am[1], wv.x, wv.y);
            }
        }
        __syncthreads();
    }
}

// grid (2, 128, 3), block 256
__global__ void __launch_bounds__(256) proj_qkv()
{
    extern __shared__ char smp[];
    const int z = blockIdx.z;
    const __half* W = g_wh + z * (CDIM * CDIM);
    const float sc = (z == 0) ? (SCALE * LOG2E) : 1.0f;
    const int m0 = blockIdx.y * 128, n0 = blockIdx.x * 128;

    ProjAcc P;
    proj_core(g_xh, W, m0, n0, smp, P);

    const int lane = threadIdx.x & 31, warp = threadIdx.x >> 5;
    const int g = lane >> 2, qd = lane & 3;
    const int wm = warp >> 1, wn = warp & 1;

    #pragma unroll
    for (int m = 0; m < 2; m++)
        #pragma unroll
        for (int rr = 0; rr < 2; rr++) {
            int mg = m0 + wm * 32 + m * 16 + g + rr * 8;
            int b = mg >> 12, n = mg & (SEQ - 1);
            #pragma unroll
            for (int nn = 0; nn < 8; nn++) {
                int col = n0 + wn * 64 + nn * 8 + qd * 2;
                int h = col >> 6, d = col & 63;
                float v0 = P.c[m][nn][rr * 2 + 0] * sc;
                float v1 = P.c[m][nn][rr * 2 + 1] * sc;
                size_t bh = (size_t)(b * HEADS + h);
                if (z < 2) {
                    // Q/K: k-pack along d (j=d>>1)
                    int j = d >> 1;
                    int c8 = ((j >> 3) << 2) | (j & 3);
                    int slot = (j >> 2) & 1;
                    __half2* dst2 = (__half2*)((z == 0) ? g_qh : g_kh);
                    dst2[(bh * SEQ + n) * 32 + c8 * 2 + slot] =
                        __floats2half2_rn(v0, v1);
                } else {
                    // V: adjacent-kv half2 with (q,q+4) interleave
                    int r = n >> 1, a = r >> 3, q = r & 7;
                    int slot = q >> 2, s = (a << 2) | (q & 3);
                    size_t baseh = ((bh * (SEQ / 4) + s) * 64 + d) * 4 + slot * 2 + (n & 1);
                    g_vh[baseh]     = __float2half_rn(v0);
                    g_vh[baseh + 4] = __float2half_rn(v1);
                }
            }
        }
}

// grid (2, 128), block 256
__global__ void __launch_bounds__(256) proj_out(const float* __restrict__ bp,
                                                float* __restrict__ out)
{
    extern __shared__ char smp[];
    const int m0 = blockIdx.y * 128, n0 = blockIdx.x * 128;

    ProjAcc P;
    proj_core(g_aoh, g_wh + 3 * (CDIM * CDIM), m0, n0, smp, P);

    const int lane = threadIdx.x & 31, warp = threadIdx.x >> 5;
    const int g = lane >> 2, qd = lane & 3;
    const int wm = warp >> 1, wn = warp & 1;

    #pragma unroll
    for (int m = 0; m < 2; m++)
        #pragma unroll
        for (int rr = 0; rr < 2; rr++) {
            int mg = m0 + wm * 32 + m * 16 + g + rr * 8;
            #pragma unroll
            for (int nn = 0; nn < 8; nn++) {
                int col = n0 + wn * 64 + nn * 8 + qd * 2;
                float2 bb = *(const float2*)(bp + col);
                float2 v = make_float2(P.c[m][nn][rr * 2 + 0] + bb.x,
                                       P.c[m][nn][rr * 2 + 1] + bb.y);
                *(float2*)&out[(size_t)mg * CDIM + col] = v;
            }
        }
}

// ---------------------------------------------------------------------------
// fp16 mma.sync flash attention: m16n8k16, 3-stage cp.async pipeline, one
// barrier per tile, shuffle-free P feed (f16x2 cvt only), ex2 softmax.
// grid = (SEQ/128, BH), block = 128, 2 CTAs/SM
// ---------------------------------------------------------------------------
__global__ void __launch_bounds__(128, 2) attn_mma()
{
    extern __shared__ char sm[];
    const int tid = threadIdx.x, lane = tid & 31, warp = tid >> 5;
    const int g = lane >> 2, qd = lane & 3;
    const int bh = blockIdx.y, q0 = blockIdx.x * 128;

    const __half* kg = g_kh + (size_t)bh * SEQ * HDIM;
    const __half* vg = g_vh + (size_t)bh * SEQ * HDIM;

    // persistent Q A-fragments: qf[m][t] = {a0,a1,a2,a3} for k-chunk t
    uint32_t qf[2][4][4];
    #pragma unroll
    for (int m = 0; m < 2; m++) {
        const uint2* qpa = (const uint2*)(g_qh +
            (((size_t)bh * SEQ + q0 + warp * 32 + m * 16 + g) << 6));
        const uint2* qpb = (const uint2*)(g_qh +
            (((size_t)bh * SEQ + q0 + warp * 32 + m * 16 + g + 8) << 6));
        #pragma unroll
        for (int t = 0; t < 4; t++) {
            uint2 ua = qpa[t * 4 + qd];
            uint2 ub = qpb[t * 4 + qd];
            qf[m][t][0] = ua.x; qf[m][t][1] = ub.x;
            qf[m][t][2] = ua.y; qf[m][t][3] = ub.y;
        }
    }

    float o[2][8][4] = {};
    float ls[4] = {0.f, 0.f, 0.f, 0.f};

    const uint32_t smb = smem_u32(sm);

    auto stage = [&](int t4, int buf) {
        uint32_t kdst = smb + (uint32_t)buf * BUFBYTES;
        uint32_t vdst = kdst + KBYTES;
        int j0 = t4 * 64;
        #pragma unroll
        for (int i = 0; i < 4; i++) {
            int idx = i * 128 + tid;
            int r = idx >> 3, c = idx & 7;
            cpa16(kdst + (uint32_t)(r * 160 + c * 16),
                  kg + (((size_t)(j0 + r)) << 6) + c * 8);
            int r2 = idx >> 5, c2 = idx & 31;
            cpa16(vdst + (uint32_t)(r2 * 544 + c2 * 16),
                  vg + (((size_t)(t4 * 16 + r2)) << 8) + c2 * 8);
        }
    };

    stage(0, 0);
    asm volatile("cp.async.commit_group;" ::: "memory");
    stage(1, 1);
    asm volatile("cp.async.commit_group;" ::: "memory");

    int buf = 0, bnext = 2;

    for (int t = 0; t < NT; t++) {
        if (t < NT - 1) {
            asm volatile("cp.async.wait_group 1;" ::: "memory");
        } else {
            asm volatile("cp.async.wait_group 0;" ::: "memory");
        }
        __syncthreads();   // tile t visible; frees buffer bnext

        if (t + 2 < NT) {
            stage(t + 2, bnext);
            asm volatile("cp.async.commit_group;" ::: "memory");
        }

        const uint2* Ks8 = (const uint2*)(sm + buf * BUFBYTES);
        const uint2* Vs8 = (const uint2*)(sm + buf * BUFBYTES + KBYTES);

        #pragma unroll
        for (int p = 0; p < 4; p++) {
            // ---- S for nn = 2p, 2p+1 ----
            float e[2][2][4];
            #pragma unroll
            for (int sub = 0; sub < 2; sub++) {
                int nn = 2 * p + sub;
                float c0[4] = {}, c1[4] = {};
                const uint2* kb = Ks8 + (nn * 8 + g) * KSTR8 + qd;
                #pragma unroll
                for (int tc = 0; tc < 4; tc++) {
                    uint2 kv2 = kb[tc * 4];
                    mma_f16(c0, qf[0][tc], kv2.x, kv2.y);
                    mma_f16(c1, qf[1][tc], kv2.x, kv2.y);
                }
                #pragma unroll
                for (int i = 0; i < 4; i++) {
                    e[sub][0][i] = ex2f(c0[i]);
                    e[sub][1][i] = ex2f(c1[i]);
                }
                ls[0] += e[sub][0][0] + e[sub][0][1];
                ls[1] += e[sub][0][2] + e[sub][0][3];
                ls[2] += e[sub][1][0] + e[sub][1][1];
                ls[3] += e[sub][1][2] + e[sub][1][3];
            }

            // ---- P A-fragments: pure f16x2 packing, no shuffles ----
            uint32_t pa[2][4];
            #pragma unroll
            for (int m = 0; m < 2; m++) {
                pa[m][0] = h2u(__floats2half2_rn(e[0][m][0], e[0][m][1]));
                pa[m][1] = h2u(__floats2half2_rn(e[0][m][2], e[0][m][3]));
                pa[m][2] = h2u(__floats2half2_rn(e[1][m][0], e[1][m][1]));
                pa[m][3] = h2u(__floats2half2_rn(e[1][m][2], e[1][m][3]));
            }

            // ---- O += P V (kv chunk 16p..16p+15) ----
            const uint2* vb = Vs8 + (p * 4 + qd) * VSTR8 + g;
            #pragma unroll
            for (int dn = 0; dn < 8; dn++) {
                uint2 vv = vb[dn * 8];
                mma_f16(o[0][dn], pa[0], vv.x, vv.y);
                mma_f16(o[1][dn], pa[1], vv.x, vv.y);
            }
        }

        buf = (buf == 2) ? 0 : buf + 1;
        bnext = (bnext == 2) ? 0 : bnext + 1;
    }

    #pragma unroll
    for (int i = 0; i < 4; i++) {
        ls[i] += __shfl_xor_sync(0xffffffffu, ls[i], 1);
        ls[i] += __shfl_xor_sync(0xffffffffu, ls[i], 2);
    }

    const int b = bh >> 2, h = bh & 3;
    #pragma unroll
    for (int m = 0; m < 2; m++)
        #pragma unroll
        for (int rr = 0; rr < 2; rr++) {
            int row = q0 + warp * 32 + m * 16 + g + rr * 8;
            float iv = 1.f / ls[m * 2 + rr];
            __half2* aop = (__half2*)g_aoh + (size_t)(b * SEQ + row) * 128;
            #pragma unroll
            for (int dn = 0; dn < 8; dn++) {
                int c = h * 64 + dn * 8 + qd * 2;
                int j = c >> 1;
                int c8 = ((j >> 3) << 2) | (j & 3);
                int slot = (j >> 2) & 1;
                aop[c8 * 2 + slot] =
                    __floats2half2_rn(o[m][dn][rr * 2 + 0] * iv,
                                      o[m][dn][rr * 2 + 1] * iv);
            }
        }
}

// ---------------------------------------------------------------------------
extern "C" void kernel_launch(void* const* d_in, const int* in_sizes, int n_in,
                              void* d_out, int out_size)
{
    (void)in_sizes; (void)n_in; (void)out_size;
    const float* x  = (const float*)d_in[0];
    const float* Wq = (const float*)d_in[1];
    const float* Wk = (const float*)d_in[2];
    const float* Wv = (const float*)d_in[3];
    const float* Wp = (const float*)d_in[4];
    const float* bp = (const float*)d_in[5];
    float* out = (float*)d_out;

    cudaFuncSetAttribute(proj_qkv, cudaFuncAttributeMaxDynamicSharedMemorySize, SMEM_PROJ);
    cudaFuncSetAttribute(proj_out, cudaFuncAttributeMaxDynamicSharedMemorySize, SMEM_PROJ);
    cudaFuncSetAttribute(attn_mma, cudaFuncAttributeMaxDynamicSharedMemorySize, SMEM_ATTN);

    pack_f16<<<(PACKTOT + 255) / 256, 256>>>(x, Wq, Wk, Wv, Wp);

    dim3 gq(CDIM / 128, (BATCH * SEQ) / 128, 3);
    proj_qkv<<<gq, 256, SMEM_PROJ>>>();

    dim3 ga(SEQ / 128, BH);
    attn_mma<<<ga, 128, SMEM_ATTN>>>();

    dim3 go(CDIM / 128, (BATCH * SEQ) / 128);
    proj_out<<<go, 256, SMEM_PROJ>>>(bp, out);
}